// round 2
// baseline (speedup 1.0000x reference)
#include <cuda_runtime.h>

#define IN_UNITS 256
#define H1 128
#define H2 64
#define EPB 64            // edges per tile
#define MAX_ROWS 16384

// Scratch (no cudaMalloc allowed): precomputed per-node layer-1 partials.
// __align__(16): float4 gather loads require 16B alignment; plain __device__
// float arrays only guarantee 4B.
__device__ __align__(16) float g_A[MAX_ROWS * H1];   // drug_feat @ W1[0:256] + b1
__device__ __align__(16) float g_B[MAX_ROWS * H1];   // dis_feat  @ W1[256:512]

// ---------------------------------------------------------------------------
// Kernel 1: precompute  outPre[r][j] = sum_k feat[r][k] * W1part[k][j] (+ b1[j])
// 16 rows x 128 cols per CTA, 256 threads.
// ---------------------------------------------------------------------------
__global__ void __launch_bounds__(256) precompute_kernel(
    const float* __restrict__ feat, const float* __restrict__ W1part,
    const float* __restrict__ b1, float* __restrict__ outPre,
    int nrows, int add_bias)
{
    __shared__ float sfeat[16][IN_UNITS];
    const int row0 = blockIdx.x * 16;
    const int tid  = threadIdx.x;

    // Stage 16x256 feature tile (float4, coalesced)
    const int total4 = 16 * IN_UNITS / 4;
    for (int l = tid; l < total4; l += 256) {
        int r  = l / (IN_UNITS / 4);
        int c4 = l % (IN_UNITS / 4);
        float4 v = make_float4(0.f, 0.f, 0.f, 0.f);
        if (row0 + r < nrows)
            v = ((const float4*)(feat + (size_t)(row0 + r) * IN_UNITS))[c4];
        ((float4*)&sfeat[r][0])[c4] = v;
    }
    __syncthreads();

    const int j  = tid & 127;   // output column
    const int rh = tid >> 7;    // row half (0/1), rows rh*8..rh*8+7
    float acc[8];
    float bb = add_bias ? b1[j] : 0.f;
#pragma unroll
    for (int i = 0; i < 8; i++) acc[i] = bb;

#pragma unroll 4
    for (int k = 0; k < IN_UNITS; k++) {
        float w = __ldg(W1part + k * H1 + j);   // coalesced, L2-resident
#pragma unroll
        for (int i = 0; i < 8; i++)
            acc[i] += sfeat[rh * 8 + i][k] * w;  // smem broadcast
    }

#pragma unroll
    for (int i = 0; i < 8; i++) {
        int r = row0 + rh * 8 + i;
        if (r < nrows) outPre[(size_t)r * H1 + j] = acc[i];
    }
}

// ---------------------------------------------------------------------------
// packed fp32x2 helpers (ptxas will not emit FFMA2 from C++)
// ---------------------------------------------------------------------------
__device__ __forceinline__ void ffma2(unsigned long long& d,
                                      unsigned long long a,
                                      unsigned long long b) {
    asm("fma.rn.f32x2 %0, %1, %2, %0;" : "+l"(d) : "l"(a), "l"(b));
}
__device__ __forceinline__ unsigned long long pack2(float x, float y) {
    unsigned long long p;
    asm("mov.b64 %0, {%1,%2};" : "=l"(p) : "f"(x), "f"(y));
    return p;
}
__device__ __forceinline__ void unpack2(unsigned long long p, float& x, float& y) {
    asm("mov.b64 {%0,%1}, %2;" : "=f"(x), "=f"(y) : "l"(p));
}

// ---------------------------------------------------------------------------
// Kernel 2: per-edge MLP.
// Persistent CTAs, 256 threads, 64 edges/tile.
// Phase A: h1[k][e] = relu(A[src[e]][k] + B[dst[e]][k])   (transposed in smem)
// Phase B: h2 = relu(h1 @ W2 + b2); out = h2 @ W3 + b3    (f32x2 FMAs)
// Thread (eg = tid>>4, og = tid&15) owns 4 edges x 4 outputs.
// NOTE: src/dst are int32 — JAX without x64 downcasts jnp.int64 to int32.
// ---------------------------------------------------------------------------
__global__ void __launch_bounds__(256, 2) edge_kernel(
    const int* __restrict__ src, const int* __restrict__ dst,
    const float* __restrict__ W2, const float* __restrict__ b2,
    const float* __restrict__ W3, const float* __restrict__ b3,
    float* __restrict__ out, int E, int ntiles)
{
    extern __shared__ char smem_raw[];
    float*  h1s = (float*)smem_raw;                          // [128][64] transposed
    float2* w2d = (float2*)(smem_raw + H1 * EPB * 4);        // [128][64] duplicated pairs

    const int tid = threadIdx.x;

    // Stage W2 once per CTA, duplicated into both f32x2 lanes
    for (int l = tid; l < H1 * H2; l += 256) {
        float w = W2[l];
        w2d[l] = make_float2(w, w);
    }

    const int og = tid & 15;     // output group: outs og*4 .. og*4+3
    const int eg = tid >> 4;     // edge group:  edges eg*4 .. eg*4+3
    const float4 b2v = *(const float4*)(b2 + og * 4);
    const float4 w3v = *(const float4*)(W3 + og * 4);
    const float  b3s = b3[0];

    const int e = tid & 63;      // phase-A edge
    const int q = tid >> 6;      // phase-A k-chunk (q*32 .. q*32+31)

    __syncthreads();

    for (int tile = blockIdx.x; tile < ntiles; tile += gridDim.x) {
        const int base = tile * EPB;

        // ---- Phase A: gather + add + relu into transposed smem ----
        {
            const int eidx = base + e;
            if (eidx < E) {
                const int s = src[eidx];
                const int d = dst[eidx];
                const float4* Ar = (const float4*)(g_A + (size_t)s * H1) + q * 8;
                const float4* Br = (const float4*)(g_B + (size_t)d * H1) + q * 8;
#pragma unroll
                for (int i = 0; i < 8; i++) {
                    float4 a = Ar[i];
                    float4 b = Br[i];
                    const int kk = q * 32 + i * 4;
                    h1s[(kk + 0) * EPB + e] = fmaxf(a.x + b.x, 0.f);
                    h1s[(kk + 1) * EPB + e] = fmaxf(a.y + b.y, 0.f);
                    h1s[(kk + 2) * EPB + e] = fmaxf(a.z + b.z, 0.f);
                    h1s[(kk + 3) * EPB + e] = fmaxf(a.w + b.w, 0.f);
                }
            } else {
#pragma unroll
                for (int i = 0; i < 8; i++) {
                    const int kk = q * 32 + i * 4;
                    h1s[(kk + 0) * EPB + e] = 0.f;
                    h1s[(kk + 1) * EPB + e] = 0.f;
                    h1s[(kk + 2) * EPB + e] = 0.f;
                    h1s[(kk + 3) * EPB + e] = 0.f;
                }
            }
        }
        __syncthreads();

        // ---- Phase B: 4 edges x 4 outputs per thread, packed f32x2 ----
        unsigned long long acc[2][4];
#pragma unroll
        for (int ep = 0; ep < 2; ep++)
#pragma unroll
            for (int oo = 0; oo < 4; oo++) acc[ep][oo] = 0ULL;

        const float4*     h1v4 = (const float4*)h1s;          // 16 float4 per k-row
        const ulonglong2* w2u  = (const ulonglong2*)w2d;      // 32 u64x2 per k-row

#pragma unroll 8
        for (int k = 0; k < H1; k++) {
            float4 hv = h1v4[k * 16 + eg];                    // edges eg*4..+3 at this k
            unsigned long long h01 = pack2(hv.x, hv.y);
            unsigned long long h23 = pack2(hv.z, hv.w);
            ulonglong2 w01 = w2u[k * 32 + og * 2];            // outs og*4, og*4+1 (dup)
            ulonglong2 w23 = w2u[k * 32 + og * 2 + 1];        // outs og*4+2, og*4+3

            ffma2(acc[0][0], h01, w01.x);
            ffma2(acc[0][1], h01, w01.y);
            ffma2(acc[0][2], h01, w23.x);
            ffma2(acc[0][3], h01, w23.y);
            ffma2(acc[1][0], h23, w01.x);
            ffma2(acc[1][1], h23, w01.y);
            ffma2(acc[1][2], h23, w23.x);
            ffma2(acc[1][3], h23, w23.y);
        }

        // ---- Epilogue: relu(h2 + b2) dot W3, reduce over 16 og-lanes ----
        float p[4] = {0.f, 0.f, 0.f, 0.f};
        const float bb[4] = {b2v.x, b2v.y, b2v.z, b2v.w};
        const float wv[4] = {w3v.x, w3v.y, w3v.z, w3v.w};
#pragma unroll
        for (int oo = 0; oo < 4; oo++) {
            float f0, f1, f2, f3;
            unpack2(acc[0][oo], f0, f1);
            unpack2(acc[1][oo], f2, f3);
            p[0] += fmaxf(f0 + bb[oo], 0.f) * wv[oo];
            p[1] += fmaxf(f1 + bb[oo], 0.f) * wv[oo];
            p[2] += fmaxf(f2 + bb[oo], 0.f) * wv[oo];
            p[3] += fmaxf(f3 + bb[oo], 0.f) * wv[oo];
        }
#pragma unroll
        for (int off = 8; off > 0; off >>= 1) {
#pragma unroll
            for (int ee = 0; ee < 4; ee++)
                p[ee] += __shfl_down_sync(0xffffffffu, p[ee], off, 16);
        }
        if (og == 0) {
#pragma unroll
            for (int ee = 0; ee < 4; ee++) {
                int idx = base + eg * 4 + ee;
                if (idx < E) out[idx] = p[ee] + b3s;
            }
        }
        __syncthreads();   // h1s reuse next tile
    }
}

// ---------------------------------------------------------------------------
extern "C" void kernel_launch(void* const* d_in, const int* in_sizes, int n_in,
                              void* d_out, int out_size)
{
    const float* drug = (const float*)d_in[0];
    const float* dis  = (const float*)d_in[1];
    const int*   src  = (const int*)d_in[2];   // int32 (JAX x64 disabled)
    const int*   dst  = (const int*)d_in[3];
    const float* W1   = (const float*)d_in[4];
    const float* b1   = (const float*)d_in[5];
    const float* W2   = (const float*)d_in[6];
    const float* b2   = (const float*)d_in[7];
    const float* W3   = (const float*)d_in[8];
    const float* b3   = (const float*)d_in[9];

    const int n_drug = in_sizes[0] / IN_UNITS;
    const int n_dis  = in_sizes[1] / IN_UNITS;
    const int E      = in_sizes[2];

    float *gA = nullptr, *gB = nullptr;
    cudaGetSymbolAddress((void**)&gA, g_A);
    cudaGetSymbolAddress((void**)&gB, g_B);

    const size_t shmem = (size_t)H1 * EPB * 4 + (size_t)H1 * H2 * 8;  // 96 KB
    cudaFuncSetAttribute(edge_kernel, cudaFuncAttributeMaxDynamicSharedMemorySize,
                         (int)shmem);

    precompute_kernel<<<(n_drug + 15) / 16, 256>>>(drug, W1, b1, gA, n_drug, 1);
    precompute_kernel<<<(n_dis  + 15) / 16, 256>>>(dis, W1 + IN_UNITS * H1, b1, gB,
                                                   n_dis, 0);

    const int ntiles = (E + EPB - 1) / EPB;
    int grid = 296;                   // 2 persistent CTAs per SM (148 SMs)
    if (grid > ntiles) grid = ntiles;
    edge_kernel<<<grid, 256, shmem>>>(src, dst, W2, b2, W3, b3,
                                      (float*)d_out, E, ntiles);
}

// round 3
// speedup vs baseline: 1.5993x; 1.5993x over previous
#include <cuda_runtime.h>

#define IN_UNITS 256
#define H1 128
#define H2 64
#define EPB 128                    // edges per tile
#define MAX_ROWS 16384
#define BUF_FLOATS (H1 * EPB)      // 16384 floats = 64 KB

// Scratch: precomputed per-node layer-1 partials (16B-aligned for vector loads)
__device__ __align__(16) float g_A[MAX_ROWS * H1];   // drug_feat @ W1[0:256] + b1
__device__ __align__(16) float g_B[MAX_ROWS * H1];   // dis_feat  @ W1[256:512]

// ---------------------------------------------------------------------------
// Kernel 1: precompute  outPre[r][j] = sum_k feat[r][k] * W1part[k][j] (+ b1[j])
// (unchanged from R2 — verified working, ~38us)
// ---------------------------------------------------------------------------
__global__ void __launch_bounds__(256) precompute_kernel(
    const float* __restrict__ feat, const float* __restrict__ W1part,
    const float* __restrict__ b1, float* __restrict__ outPre,
    int nrows, int add_bias)
{
    __shared__ float sfeat[16][IN_UNITS];
    const int row0 = blockIdx.x * 16;
    const int tid  = threadIdx.x;

    const int total4 = 16 * IN_UNITS / 4;
    for (int l = tid; l < total4; l += 256) {
        int r  = l / (IN_UNITS / 4);
        int c4 = l % (IN_UNITS / 4);
        float4 v = make_float4(0.f, 0.f, 0.f, 0.f);
        if (row0 + r < nrows)
            v = ((const float4*)(feat + (size_t)(row0 + r) * IN_UNITS))[c4];
        ((float4*)&sfeat[r][0])[c4] = v;
    }
    __syncthreads();

    const int j  = tid & 127;
    const int rh = tid >> 7;
    float acc[8];
    float bb = add_bias ? b1[j] : 0.f;
#pragma unroll
    for (int i = 0; i < 8; i++) acc[i] = bb;

#pragma unroll 4
    for (int k = 0; k < IN_UNITS; k++) {
        float w = __ldg(W1part + k * H1 + j);
#pragma unroll
        for (int i = 0; i < 8; i++)
            acc[i] += sfeat[rh * 8 + i][k] * w;
    }

#pragma unroll
    for (int i = 0; i < 8; i++) {
        int r = row0 + rh * 8 + i;
        if (r < nrows) outPre[(size_t)r * H1 + j] = acc[i];
    }
}

// ---------------------------------------------------------------------------
// packed fp32x2 helpers (ptxas never emits FFMA2/FADD2 from C++)
// ---------------------------------------------------------------------------
__device__ __forceinline__ void ffma2(unsigned long long& d,
                                      unsigned long long a,
                                      unsigned long long b) {
    asm("fma.rn.f32x2 %0, %1, %2, %0;" : "+l"(d) : "l"(a), "l"(b));
}
__device__ __forceinline__ unsigned long long add2(unsigned long long a,
                                                   unsigned long long b) {
    unsigned long long r;
    asm("add.rn.f32x2 %0, %1, %2;" : "=l"(r) : "l"(a), "l"(b));
    return r;
}
__device__ __forceinline__ unsigned long long pack2(float x, float y) {
    unsigned long long p;
    asm("mov.b64 %0, {%1,%2};" : "=l"(p) : "f"(x), "f"(y));
    return p;
}
__device__ __forceinline__ void unpack2(unsigned long long p, float& x, float& y) {
    asm("mov.b64 {%0,%1}, %2;" : "=f"(x), "=f"(y) : "l"(p));
}

// ---------------------------------------------------------------------------
// Kernel 2: per-edge MLP, software-pipelined.
// 256 threads, 1 CTA/SM (192 KB smem), EPB=128 edges/tile.
// Thread (og = tid&7, eg = tid>>3) owns 4 edges x 8 outputs.
// Mainloop per k: 1 LDS.128 (h, 4 edges) + 4 LDS.128 (w2i dup'd, conflict-free)
//                 + 2 packs + 16 FFMA2  -> FMA-pipe bound.
// Next tile's gather (L2-resident g_A/g_B) interleaved in 8 chunks.
// ---------------------------------------------------------------------------
__global__ void __launch_bounds__(256, 1) edge_kernel(
    const int* __restrict__ src, const int* __restrict__ dst,
    const float* __restrict__ W2, const float* __restrict__ b2,
    const float* __restrict__ W3, const float* __restrict__ b3,
    float* __restrict__ out, int E, int ntiles)
{
    extern __shared__ char smem_raw[];
    float* hbuf0 = (float*)smem_raw;                       // [128 k][128 e]
    float* hbuf1 = hbuf0 + BUF_FLOATS;
    float2* w2f2 = (float2*)(smem_raw + 2 * BUF_FLOATS * 4);   // dup'd interleaved, 64 KB
    const ulonglong2* w2u = (const ulonglong2*)w2f2;

    const int tid = threadIdx.x;

    // Stage W2 interleaved + duplicated: element (k, j, og) = ulonglong2 holding
    // dup'd weights for outs (og*8 + 2j, og*8 + 2j + 1).
    for (int l = tid; l < H1 * H2; l += 256) {
        int k = l >> 6, o_out = l & 63;
        int og = o_out >> 3, o = o_out & 7, j = o >> 1, half = o & 1;
        float w = W2[l];
        w2f2[(((k * 4 + j) << 3) + og) * 2 + half] = make_float2(w, w);
    }

    const int og = tid & 7;      // outputs og*8 .. og*8+7
    const int eg = tid >> 3;     // edges eg*4 .. eg*4+3  (0..31)
    const int e  = tid & 127;    // gather: this thread's edge within tile
    const int q  = tid >> 7;     // gather: k-half (0/1)

    float bb[8], w3r[8];
    {
        float4 a0 = ((const float4*)b2)[og * 2];
        float4 a1 = ((const float4*)b2)[og * 2 + 1];
        float4 c0 = ((const float4*)W3)[og * 2];
        float4 c1 = ((const float4*)W3)[og * 2 + 1];
        bb[0]=a0.x; bb[1]=a0.y; bb[2]=a0.z; bb[3]=a0.w;
        bb[4]=a1.x; bb[5]=a1.y; bb[6]=a1.z; bb[7]=a1.w;
        w3r[0]=c0.x; w3r[1]=c0.y; w3r[2]=c0.z; w3r[3]=c0.w;
        w3r[4]=c1.x; w3r[5]=c1.y; w3r[6]=c1.z; w3r[7]=c1.w;
    }
    const float b3s = b3[0];

    int tile = blockIdx.x;
    const int stride = gridDim.x;

    // ---- Prologue: gather tile -> hbuf0 ----
    {
        int ei = tile * EPB + e;
        if (ei >= E) ei = E - 1;               // clamp: garbage h, store guarded
        const int s = src[ei], d = dst[ei];
        const float* Ab = g_A + (size_t)s * H1;
        const float* Bb = g_B + (size_t)d * H1;
#pragma unroll
        for (int c = 0; c < 8; c++) {
            const int kb = c * 16 + q * 8;
            ulonglong2 ga0 = ((const ulonglong2*)(Ab + kb))[0];
            ulonglong2 ga1 = ((const ulonglong2*)(Ab + kb))[1];
            ulonglong2 gb0 = ((const ulonglong2*)(Bb + kb))[0];
            ulonglong2 gb1 = ((const ulonglong2*)(Bb + kb))[1];
            unsigned long long r0 = add2(ga0.x, gb0.x);
            unsigned long long r1 = add2(ga0.y, gb0.y);
            unsigned long long r2 = add2(ga1.x, gb1.x);
            unsigned long long r3 = add2(ga1.y, gb1.y);
            float f0,f1,f2,f3,f4,f5,f6,f7;
            unpack2(r0,f0,f1); unpack2(r1,f2,f3);
            unpack2(r2,f4,f5); unpack2(r3,f6,f7);
            hbuf0[(kb+0)*EPB + e] = fmaxf(f0,0.f);
            hbuf0[(kb+1)*EPB + e] = fmaxf(f1,0.f);
            hbuf0[(kb+2)*EPB + e] = fmaxf(f2,0.f);
            hbuf0[(kb+3)*EPB + e] = fmaxf(f3,0.f);
            hbuf0[(kb+4)*EPB + e] = fmaxf(f4,0.f);
            hbuf0[(kb+5)*EPB + e] = fmaxf(f5,0.f);
            hbuf0[(kb+6)*EPB + e] = fmaxf(f6,0.f);
            hbuf0[(kb+7)*EPB + e] = fmaxf(f7,0.f);
        }
    }
    __syncthreads();

    float* bufp = hbuf0;
    float* bufn = hbuf1;

    for (; tile < ntiles; tile += stride) {
        const int next = tile + stride;
        const bool do_next = (next < ntiles);

        // next tile's gather base pointers
        const float *Ab = g_A, *Bb = g_B;
        if (do_next) {
            int ei = next * EPB + e;
            if (ei >= E) ei = E - 1;
            Ab = g_A + (size_t)src[ei] * H1;
            Bb = g_B + (size_t)dst[ei] * H1;
        }

        unsigned long long acc[2][8];
#pragma unroll
        for (int ep = 0; ep < 2; ep++)
#pragma unroll
            for (int o = 0; o < 8; o++) acc[ep][o] = 0ULL;

        const float4* hv4 = (const float4*)bufp;
        ulonglong2 GA[2][2], GB[2][2];

#pragma unroll
        for (int c = 0; c < 8; c++) {
            // (1) issue LDGs for next-tile chunk c (latency hidden by FMA block)
            if (do_next) {
                const int kb = c * 16 + q * 8;
                GA[c & 1][0] = ((const ulonglong2*)(Ab + kb))[0];
                GA[c & 1][1] = ((const ulonglong2*)(Ab + kb))[1];
                GB[c & 1][0] = ((const ulonglong2*)(Bb + kb))[0];
                GB[c & 1][1] = ((const ulonglong2*)(Bb + kb))[1];
            }

            // (2) FMA block: k = c*16 .. c*16+16 on current buffer
#pragma unroll
            for (int kk = 0; kk < 16; kk++) {
                const int k = c * 16 + kk;
                float4 hv = hv4[k * (EPB / 4) + eg];
                unsigned long long h01 = pack2(hv.x, hv.y);
                unsigned long long h23 = pack2(hv.z, hv.w);
#pragma unroll
                for (int j = 0; j < 4; j++) {
                    ulonglong2 wv = w2u[((k * 4 + j) << 3) + og];
                    ffma2(acc[0][2*j],   h01, wv.x);
                    ffma2(acc[0][2*j+1], h01, wv.y);
                    ffma2(acc[1][2*j],   h23, wv.x);
                    ffma2(acc[1][2*j+1], h23, wv.y);
                }
            }

            // (3) combine+store PREVIOUS chunk's gathered data into next buffer
            if (do_next && c > 0) {
                const int pb = (c - 1) & 1;
                const int kb = (c - 1) * 16 + q * 8;
#pragma unroll
                for (int i = 0; i < 2; i++) {
                    unsigned long long r0 = add2(GA[pb][i].x, GB[pb][i].x);
                    unsigned long long r1 = add2(GA[pb][i].y, GB[pb][i].y);
                    float f0,f1,f2,f3;
                    unpack2(r0,f0,f1); unpack2(r1,f2,f3);
                    bufn[(kb+4*i+0)*EPB + e] = fmaxf(f0,0.f);
                    bufn[(kb+4*i+1)*EPB + e] = fmaxf(f1,0.f);
                    bufn[(kb+4*i+2)*EPB + e] = fmaxf(f2,0.f);
                    bufn[(kb+4*i+3)*EPB + e] = fmaxf(f3,0.f);
                }
            }
        }
        // store final gathered chunk (c = 7)
        if (do_next) {
            const int kb = 7 * 16 + q * 8;
#pragma unroll
            for (int i = 0; i < 2; i++) {
                unsigned long long r0 = add2(GA[1][i].x, GB[1][i].x);
                unsigned long long r1 = add2(GA[1][i].y, GB[1][i].y);
                float f0,f1,f2,f3;
                unpack2(r0,f0,f1); unpack2(r1,f2,f3);
                bufn[(kb+4*i+0)*EPB + e] = fmaxf(f0,0.f);
                bufn[(kb+4*i+1)*EPB + e] = fmaxf(f1,0.f);
                bufn[(kb+4*i+2)*EPB + e] = fmaxf(f2,0.f);
                bufn[(kb+4*i+3)*EPB + e] = fmaxf(f3,0.f);
            }
        }

        // ---- Epilogue: relu(h2+b2) . W3, reduce over 8 og-lanes ----
        float p[4] = {0.f, 0.f, 0.f, 0.f};
#pragma unroll
        for (int o = 0; o < 8; o++) {
            float f0,f1,f2,f3;
            unpack2(acc[0][o], f0, f1);
            unpack2(acc[1][o], f2, f3);
            p[0] += fmaxf(f0 + bb[o], 0.f) * w3r[o];
            p[1] += fmaxf(f1 + bb[o], 0.f) * w3r[o];
            p[2] += fmaxf(f2 + bb[o], 0.f) * w3r[o];
            p[3] += fmaxf(f3 + bb[o], 0.f) * w3r[o];
        }
#pragma unroll
        for (int off = 4; off > 0; off >>= 1) {
#pragma unroll
            for (int ee = 0; ee < 4; ee++)
                p[ee] += __shfl_down_sync(0xffffffffu, p[ee], off, 8);
        }
        if (og == 0) {
            const int base = tile * EPB + eg * 4;
#pragma unroll
            for (int ee = 0; ee < 4; ee++)
                if (base + ee < E) out[base + ee] = p[ee] + b3s;
        }

        __syncthreads();            // all reads of bufp & writes to bufn done
        float* t = bufp; bufp = bufn; bufn = t;
    }
}

// ---------------------------------------------------------------------------
extern "C" void kernel_launch(void* const* d_in, const int* in_sizes, int n_in,
                              void* d_out, int out_size)
{
    const float* drug = (const float*)d_in[0];
    const float* dis  = (const float*)d_in[1];
    const int*   src  = (const int*)d_in[2];   // int32 (JAX x64 disabled)
    const int*   dst  = (const int*)d_in[3];
    const float* W1   = (const float*)d_in[4];
    const float* b1   = (const float*)d_in[5];
    const float* W2   = (const float*)d_in[6];
    const float* b2   = (const float*)d_in[7];
    const float* W3   = (const float*)d_in[8];
    const float* b3   = (const float*)d_in[9];

    const int n_drug = in_sizes[0] / IN_UNITS;
    const int n_dis  = in_sizes[1] / IN_UNITS;
    const int E      = in_sizes[2];

    float *gA = nullptr, *gB = nullptr;
    cudaGetSymbolAddress((void**)&gA, g_A);
    cudaGetSymbolAddress((void**)&gB, g_B);

    const size_t shmem = 2 * (size_t)BUF_FLOATS * 4 + (size_t)H1 * H2 * 8;  // 192 KB
    cudaFuncSetAttribute(edge_kernel, cudaFuncAttributeMaxDynamicSharedMemorySize,
                         (int)shmem);

    precompute_kernel<<<(n_drug + 15) / 16, 256>>>(drug, W1, b1, gA, n_drug, 1);
    precompute_kernel<<<(n_dis  + 15) / 16, 256>>>(dis, W1 + IN_UNITS * H1, b1, gB,
                                                   n_dis, 0);

    const int ntiles = (E + EPB - 1) / EPB;
    int grid = 148;                  // 1 persistent CTA per SM
    if (grid > ntiles) grid = ntiles;
    edge_kernel<<<grid, 256, shmem>>>(src, dst, W2, b2, W3, b3,
                                      (float*)d_out, E, ntiles);
}

// round 5
// speedup vs baseline: 5.8397x; 3.6514x over previous
#include <cuda_runtime.h>
#include <cuda_bf16.h>
#include <cstdint>

#define IN_UNITS 256
#define H1 128
#define H2 64
#define MAX_ROWS 16384

// smem layout (bytes). Padded strides: 272 = 256+16, 144 = 128+16 -> ldmatrix
// 8-row phases hit distinct banks (stride 4 banks/row).
#define H1_STRIDE 272
#define W2_STRIDE 144
#define OFF_H1HI 0
#define OFF_H1LO (128 * H1_STRIDE)                 // 34816
#define OFF_W2HI (2 * 128 * H1_STRIDE)             // 69632
#define OFF_W2LO (OFF_W2HI + 128 * W2_STRIDE)      // 88064
#define OFF_BW   (OFF_W2LO + 128 * W2_STRIDE)      // 106496
#define SMEM_TOTAL (OFF_BW + 64 * 8)               // 107008 -> 2 CTAs/SM

__device__ __align__(16) float g_A[MAX_ROWS * H1];   // drug @ W1_top + b1
__device__ __align__(16) float g_B[MAX_ROWS * H1];   // dis  @ W1_bot

// ---------------------------------------------------------------------------
// Kernel 1: per-node layer-1 partials. W-loads batched 8-wide for MLP.
// ---------------------------------------------------------------------------
__global__ void __launch_bounds__(256) precompute_kernel(
    const float* __restrict__ feat, const float* __restrict__ W1part,
    const float* __restrict__ b1, float* __restrict__ outPre,
    int nrows, int add_bias)
{
    __shared__ float sfeat[16][IN_UNITS];
    const int row0 = blockIdx.x * 16;
    const int tid  = threadIdx.x;

    const int total4 = 16 * IN_UNITS / 4;
    for (int l = tid; l < total4; l += 256) {
        int r  = l / (IN_UNITS / 4);
        int c4 = l % (IN_UNITS / 4);
        float4 v = make_float4(0.f, 0.f, 0.f, 0.f);
        if (row0 + r < nrows)
            v = ((const float4*)(feat + (size_t)(row0 + r) * IN_UNITS))[c4];
        ((float4*)&sfeat[r][0])[c4] = v;
    }
    __syncthreads();

    const int j  = tid & 127;
    const int rh = tid >> 7;
    float acc[8];
    float bb = add_bias ? b1[j] : 0.f;
#pragma unroll
    for (int i = 0; i < 8; i++) acc[i] = bb;

    for (int k0 = 0; k0 < IN_UNITS; k0 += 8) {
        float w[8];
#pragma unroll
        for (int jj = 0; jj < 8; jj++)
            w[jj] = __ldg(W1part + (k0 + jj) * H1 + j);   // 8 LDG in flight
#pragma unroll
        for (int jj = 0; jj < 8; jj++)
#pragma unroll
            for (int i = 0; i < 8; i++)
                acc[i] += sfeat[rh * 8 + i][k0 + jj] * w[jj];
    }

#pragma unroll
    for (int i = 0; i < 8; i++) {
        int r = row0 + rh * 8 + i;
        if (r < nrows) outPre[(size_t)r * H1 + j] = acc[i];
    }
}

// ---------------------------------------------------------------------------
// mma.sync / ldmatrix helpers (baseline sm_80+ features; compile on sm_103)
// ---------------------------------------------------------------------------
__device__ __forceinline__ uint32_t smem_u32(const void* p) {
    uint32_t a;
    asm("{ .reg .u64 t; cvta.to.shared.u64 t, %1; cvt.u32.u64 %0, t; }"
        : "=r"(a) : "l"(p));
    return a;
}
__device__ __forceinline__ void ldsm_x4(uint32_t* r, uint32_t a) {
    asm volatile("ldmatrix.sync.aligned.m8n8.x4.shared.b16 {%0,%1,%2,%3}, [%4];"
                 : "=r"(r[0]), "=r"(r[1]), "=r"(r[2]), "=r"(r[3]) : "r"(a));
}
__device__ __forceinline__ void ldsm_x4_t(uint32_t* r, uint32_t a) {
    asm volatile("ldmatrix.sync.aligned.m8n8.x4.trans.shared.b16 {%0,%1,%2,%3}, [%4];"
                 : "=r"(r[0]), "=r"(r[1]), "=r"(r[2]), "=r"(r[3]) : "r"(a));
}
__device__ __forceinline__ void mma_bf16(float* c, const uint32_t* a,
                                         uint32_t b0, uint32_t b1) {
    asm volatile(
        "mma.sync.aligned.m16n8k16.row.col.f32.bf16.bf16.f32 "
        "{%0,%1,%2,%3}, {%4,%5,%6,%7}, {%8,%9}, {%0,%1,%2,%3};"
        : "+f"(c[0]), "+f"(c[1]), "+f"(c[2]), "+f"(c[3])
        : "r"(a[0]), "r"(a[1]), "r"(a[2]), "r"(a[3]), "r"(b0), "r"(b1));
}

// ---------------------------------------------------------------------------
// Kernel 2: per-edge MLP. 256 threads, 2 CTAs/SM, warp-private 16-edge tiles.
// Per warp-tile: coalesced gather (lane l = k 4l..4l+3) -> bf16 hi/lo smem ->
// ldmatrix -> 3-term split mma.sync -> layer-3 dot in regs -> STG.
// No __syncthreads in the loop; warps overlap freely.
// ---------------------------------------------------------------------------
__global__ void __launch_bounds__(256, 2) edge_kernel(
    const int* __restrict__ src, const int* __restrict__ dst,
    const float* __restrict__ W2, const float* __restrict__ b2,
    const float* __restrict__ W3, const float* __restrict__ b3,
    float* __restrict__ out, int E, int nwt)
{
    extern __shared__ char smem[];
    const int tid = threadIdx.x, wid = tid >> 5, lid = tid & 31;

    // Stage W2 hi/lo (row-major [k][n], padded rows) + (b2, W3) table
    for (int l = tid; l < H1 * H2; l += 256) {
        const int k = l >> 6, o = l & 63;
        float w = W2[l];
        __nv_bfloat16 hb = __float2bfloat16(w);
        __nv_bfloat16 lb = __float2bfloat16(w - __bfloat162float(hb));
        *(__nv_bfloat16*)(smem + OFF_W2HI + k * W2_STRIDE + o * 2) = hb;
        *(__nv_bfloat16*)(smem + OFF_W2LO + k * W2_STRIDE + o * 2) = lb;
    }
    for (int l = tid; l < H2; l += 256)
        ((float2*)(smem + OFF_BW))[l] = make_float2(b2[l], W3[l]);
    __syncthreads();

    const float b3s = __ldg(b3);
    const uint32_t sb = smem_u32(smem);

    // this warp's private h1 rows
    const uint32_t h1hi = sb + OFF_H1HI + wid * 16 * H1_STRIDE;
    const uint32_t h1lo = sb + OFF_H1LO + wid * 16 * H1_STRIDE;
    char* h1hi_p = smem + OFF_H1HI + wid * 16 * H1_STRIDE;
    char* h1lo_p = smem + OFF_H1LO + wid * 16 * H1_STRIDE;

    // ldmatrix lane->address components
    const uint32_t a_off  = (lid & 15) * H1_STRIDE + (lid >> 4) * 16;  // + ks*32
    const uint32_t b_row  = ((lid >> 3) & 1) * 8 + (lid & 7);          // + ks*16
    const uint32_t b_nt   = (lid >> 4);                                // 0/1

    const int gw = blockIdx.x * 8 + wid;
    const int gstride = gridDim.x * 8;

    for (int wt = gw; wt < nwt; wt += gstride) {
        const int e0 = wt * 16;

        // ---- gather: 16 rows, lane l covers k = 4l..4l+3 ----
#pragma unroll 4
        for (int i = 0; i < 16; i++) {
            int ei = e0 + i;
            if (ei >= E) ei = E - 1;
            const int s = __ldg(src + ei);
            const int d = __ldg(dst + ei);
            float4 av = *(const float4*)(g_A + (size_t)s * H1 + lid * 4);
            float4 bv = *(const float4*)(g_B + (size_t)d * H1 + lid * 4);
            float x0 = fmaxf(av.x + bv.x, 0.f), x1 = fmaxf(av.y + bv.y, 0.f);
            float x2 = fmaxf(av.z + bv.z, 0.f), x3 = fmaxf(av.w + bv.w, 0.f);

            __nv_bfloat162 h01 = __floats2bfloat162_rn(x0, x1);
            __nv_bfloat162 h23 = __floats2bfloat162_rn(x2, x3);
            uint32_t hb01 = *(uint32_t*)&h01, hb23 = *(uint32_t*)&h23;
            float r0 = x0 - __uint_as_float((hb01 & 0xFFFFu) << 16);
            float r1 = x1 - __uint_as_float(hb01 & 0xFFFF0000u);
            float r2 = x2 - __uint_as_float((hb23 & 0xFFFFu) << 16);
            float r3 = x3 - __uint_as_float(hb23 & 0xFFFF0000u);
            __nv_bfloat162 l01 = __floats2bfloat162_rn(r0, r1);
            __nv_bfloat162 l23 = __floats2bfloat162_rn(r2, r3);

            const uint32_t off = i * H1_STRIDE + lid * 8;
            *(uint2*)(h1hi_p + off) = make_uint2(hb01, hb23);
            *(uint2*)(h1lo_p + off) =
                make_uint2(*(uint32_t*)&l01, *(uint32_t*)&l23);
        }
        __syncwarp();   // cross-lane smem visibility before ldmatrix

        // ---- mma: 8 k-steps x 8 n-tiles x 3 split terms ----
        float acc[8][4];
#pragma unroll
        for (int nt = 0; nt < 8; nt++)
#pragma unroll
            for (int c = 0; c < 4; c++) acc[nt][c] = 0.f;

#pragma unroll
        for (int ks = 0; ks < 8; ks++) {
            uint32_t ah[4], al[4];
            ldsm_x4(ah, h1hi + a_off + ks * 32);
            ldsm_x4(al, h1lo + a_off + ks * 32);
#pragma unroll
            for (int ntp = 0; ntp < 4; ntp++) {
                const uint32_t brow = (ks * 16 + b_row) * W2_STRIDE
                                    + (ntp * 2 + b_nt) * 16;
                uint32_t bh[4], bl[4];
                ldsm_x4_t(bh, sb + OFF_W2HI + brow);
                ldsm_x4_t(bl, sb + OFF_W2LO + brow);
                mma_bf16(acc[ntp * 2],     ah, bh[0], bh[1]);
                mma_bf16(acc[ntp * 2],     al, bh[0], bh[1]);
                mma_bf16(acc[ntp * 2],     ah, bl[0], bl[1]);
                mma_bf16(acc[ntp * 2 + 1], ah, bh[2], bh[3]);
                mma_bf16(acc[ntp * 2 + 1], al, bh[2], bh[3]);
                mma_bf16(acc[ntp * 2 + 1], ah, bl[2], bl[3]);
            }
        }

        // ---- epilogue: relu(h2+b2).W3, quad reduce, store ----
        float pr = 0.f, pr8 = 0.f;
        const float2* bwt = (const float2*)(smem + OFF_BW);
#pragma unroll
        for (int nt = 0; nt < 8; nt++) {
            const int col = nt * 8 + (lid & 3) * 2;
            float2 c0 = bwt[col], c1 = bwt[col + 1];
            pr  += fmaxf(acc[nt][0] + c0.x, 0.f) * c0.y
                 + fmaxf(acc[nt][1] + c1.x, 0.f) * c1.y;
            pr8 += fmaxf(acc[nt][2] + c0.x, 0.f) * c0.y
                 + fmaxf(acc[nt][3] + c1.x, 0.f) * c1.y;
        }
        pr  += __shfl_xor_sync(0xffffffffu, pr, 1);
        pr  += __shfl_xor_sync(0xffffffffu, pr, 2);
        pr8 += __shfl_xor_sync(0xffffffffu, pr8, 1);
        pr8 += __shfl_xor_sync(0xffffffffu, pr8, 2);
        if ((lid & 3) == 0) {
            const int r = lid >> 2;
            if (e0 + r < E)     out[e0 + r]     = pr + b3s;
            if (e0 + r + 8 < E) out[e0 + r + 8] = pr8 + b3s;
        }
        __syncwarp();   // ldmatrix reads done before next tile's stores
    }
}

// ---------------------------------------------------------------------------
extern "C" void kernel_launch(void* const* d_in, const int* in_sizes, int n_in,
                              void* d_out, int out_size)
{
    const float* drug = (const float*)d_in[0];
    const float* dis  = (const float*)d_in[1];
    const int*   src  = (const int*)d_in[2];   // int32 (JAX x64 disabled)
    const int*   dst  = (const int*)d_in[3];
    const float* W1   = (const float*)d_in[4];
    const float* b1   = (const float*)d_in[5];
    const float* W2   = (const float*)d_in[6];
    const float* b2   = (const float*)d_in[7];
    const float* W3   = (const float*)d_in[8];
    const float* b3   = (const float*)d_in[9];

    const int n_drug = in_sizes[0] / IN_UNITS;
    const int n_dis  = in_sizes[1] / IN_UNITS;
    const int E      = in_sizes[2];

    float *gA = nullptr, *gB = nullptr;
    cudaGetSymbolAddress((void**)&gA, g_A);
    cudaGetSymbolAddress((void**)&gB, g_B);

    cudaFuncSetAttribute(edge_kernel, cudaFuncAttributeMaxDynamicSharedMemorySize,
                         SMEM_TOTAL);

    precompute_kernel<<<(n_drug + 15) / 16, 256>>>(drug, W1, b1, gA, n_drug, 1);
    precompute_kernel<<<(n_dis  + 15) / 16, 256>>>(dis, W1 + IN_UNITS * H1, b1, gB,
                                                   n_dis, 0);

    const int nwt = (E + 15) / 16;           // 16-edge warp-tiles
    int grid = 296;                          // 2 CTAs/SM
    if (grid > (nwt + 7) / 8) grid = (nwt + 7) / 8;
    edge_kernel<<<grid, 256, SMEM_TOTAL>>>(src, dst, W2, b2, W3, b3,
                                           (float*)d_out, E, nwt);
}